// round 14
// baseline (speedup 1.0000x reference)
#include <cuda_runtime.h>
#include <cuda_bf16.h>
#include <cstdint>

#define BB 4
#define SS 4096
#define DD 2048
#define EE 64
#define CAP 128
#define M_TOT (BB*SS)          // 16384 tokens
#define OFF_MAXP (M_TOT*EE)

#define BM 64
#define BK 32
#define NTILES (DD/BK)         // 64 total k-tiles
#define TPH 32                 // tiles per k-half (in-CTA split-K=2)
#define KPR 20                 // u32 row stride in smem (conflict-free LDS/LDSM)
#define LR 68                  // slog f32 row stride

#define TAU_FLAG 1e-3f
#define TAU_CAND 2e-3f
#define MAXFIX 8192

__device__ __align__(16) unsigned char g_eidx[M_TOT];
__device__ int g_cnt = 0;
__device__ int g_list[MAXFIX];
__device__ unsigned long long g_mask[MAXFIX];
// pre-split W, tile-major: [tile t][row e][16 u32]
__device__ __align__(16) unsigned gWh[NTILES * EE * 16];
__device__ __align__(16) unsigned gWl[NTILES * EE * 16];

// fast split: hi = bf16x2(x,y), lo = bf16x2(residuals); .rn rounding
__device__ __forceinline__ void split_pack(float x, float y, unsigned &hi, unsigned &lo) {
    unsigned H;
    asm("cvt.rn.bf16x2.f32 %0, %1, %2;" : "=r"(H) : "f"(y), "f"(x));
    float xh = __uint_as_float(H << 16);
    float yh = __uint_as_float(H & 0xffff0000u);
    float rx = x - xh, ry = y - yh;
    unsigned L;
    asm("cvt.rn.bf16x2.f32 %0, %1, %2;" : "=r"(L) : "f"(ry), "f"(rx));
    hi = H; lo = L;
}

__device__ __forceinline__ void mma16(float c[4], const unsigned a[4],
                                      unsigned b0, unsigned b1) {
    asm volatile("mma.sync.aligned.m16n8k16.row.col.f32.bf16.bf16.f32 "
                 "{%0,%1,%2,%3}, {%4,%5,%6,%7}, {%8,%9}, {%0,%1,%2,%3};"
                 : "+f"(c[0]), "+f"(c[1]), "+f"(c[2]), "+f"(c[3])
                 : "r"(a[0]), "r"(a[1]), "r"(a[2]), "r"(a[3]), "r"(b0), "r"(b1));
}

__device__ __forceinline__ void ldsm4(unsigned r[4], unsigned addr) {
    asm volatile("ldmatrix.sync.aligned.m8n8.x4.shared.b16 {%0,%1,%2,%3}, [%4];"
                 : "=r"(r[0]), "=r"(r[1]), "=r"(r[2]), "=r"(r[3]) : "r"(addr));
}

__device__ __forceinline__ unsigned smem_u32(const void* p) {
    unsigned a;
    asm("{ .reg .u64 t; cvta.to.shared.u64 t, %1; cvt.u32.u64 %0, t; }" : "=r"(a) : "l"(p));
    return a;
}

__global__ __launch_bounds__(256) void split_w(const float* __restrict__ W)
{
    int e  = blockIdx.x >> 2;
    int jg = (blockIdx.x & 3) * 256 + threadIdx.x;
    int k  = 2 * jg;
    float x = W[e * DD + k], y = W[e * DD + k + 1];
    unsigned h, l;
    split_pack(x, y, h, l);
    int t = jg >> 4, j = jg & 15;
    gWh[(t * EE + e) * 16 + j] = h;
    gWl[(t * EE + e) * 16 + j] = l;
}

__global__ __launch_bounds__(256, 2) void router_mma(
    const float* __restrict__ A,     // [M_TOT, DD]
    const float* __restrict__ bias,  // [EE]
    float* __restrict__ out)
{
    __shared__ __align__(16) unsigned smbuf[10240];   // 40 KB: 2 halves x 5120
    __shared__ float sbias[EE];
    float* slog = (float*)smbuf;      // epilogue reuse [64][LR]

    const int tid  = threadIdx.x;
    const int lane = tid & 31;
    const int wid  = tid >> 5;
    const int h    = tid >> 7;        // k-half 0/1
    const int wt   = tid & 127;       // thread within half
    const int w2   = wid & 3;         // warp within half
    const int wm   = w2 >> 1;
    const int wn   = w2 & 1;
    const int g    = lane >> 2;
    const int c    = lane & 3;
    const int blk  = blockIdx.x * BM;

    unsigned* sAh = smbuf + h * 5120;  // [64][KPR]
    unsigned* sAl = sAh + 1280;
    unsigned* sWh = sAh + 2560;
    unsigned* sWl = sAh + 3840;

    if (tid < EE) sbias[tid] = bias[tid];

    const float4* __restrict__ A4 = (const float4*)A;
    const uint4*  gWh4 = (const uint4*)gWh;
    const uint4*  gWl4 = (const uint4*)gWl;

    const int kqb = h * (DD / 4 / 2);  // float4 base offset in A row
    const int tb  = h * TPH;           // W tile base for this half

    // ldmatrix lane addresses (bytes): rows at 80B stride, 16B k-chunks
    const unsigned smb  = smem_u32(smbuf);
    const unsigned hb   = smb + h * 20480;
    const int lrow  = lane & 15;
    const int lhalf = lane >> 4;
    unsigned aAddr[2], bAddr[2];
#pragma unroll
    for (int mt = 0; mt < 2; mt++)
        aAddr[mt] = hb + (unsigned)((wm * 32 + mt * 16 + lrow) * 80 + lhalf * 16);
#pragma unroll
    for (int np = 0; np < 2; np++)
        bAddr[np] = hb + 10240u + (unsigned)((wn * 32 + np * 16 + lrow) * 80 + lhalf * 16);

    float acc[2][4][4];
#pragma unroll
    for (int mt = 0; mt < 2; mt++)
#pragma unroll
        for (int nt = 0; nt < 4; nt++)
#pragma unroll
            for (int q = 0; q < 4; q++) acc[mt][nt][q] = 0.0f;

    float4 pa[4];
    uint4  pwh[2], pwl[2];

    // ---- LDG tile 0 of this half ----
#pragma unroll
    for (int l = 0; l < 4; l++) {
        int fi = l * 128 + wt;
        int row = fi >> 3, kq = fi & 7;
        pa[l] = A4[(long)(blk + row) * (DD / 4) + kqb + kq];
    }
#pragma unroll
    for (int l = 0; l < 2; l++) {
        pwh[l] = gWh4[tb * 256 + l * 128 + wt];
        pwl[l] = gWl4[tb * 256 + l * 128 + wt];
    }
    // ---- stage tile 0 ----
#pragma unroll
    for (int l = 0; l < 4; l++) {
        int fi = l * 128 + wt;
        int row = fi >> 3, kq = fi & 7;
        unsigned h0, l0, h1, l1;
        split_pack(pa[l].x, pa[l].y, h0, l0);
        split_pack(pa[l].z, pa[l].w, h1, l1);
        *(uint2*)&sAh[row * KPR + 2 * kq] = make_uint2(h0, h1);
        *(uint2*)&sAl[row * KPR + 2 * kq] = make_uint2(l0, l1);
    }
#pragma unroll
    for (int l = 0; l < 2; l++) {
        int u = l * 128 + wt;
        int row = u >> 2, q = u & 3;
        *(uint4*)&sWh[row * KPR + q * 4] = pwh[l];
        *(uint4*)&sWl[row * KPR + q * 4] = pwl[l];
    }
    // ---- LDG tile 1 ----
#pragma unroll
    for (int l = 0; l < 4; l++) {
        int fi = l * 128 + wt;
        int row = fi >> 3, kq = fi & 7;
        pa[l] = A4[(long)(blk + row) * (DD / 4) + kqb + 8 + kq];
    }
#pragma unroll
    for (int l = 0; l < 2; l++) {
        pwh[l] = gWh4[(tb + 1) * 256 + l * 128 + wt];
        pwl[l] = gWl4[(tb + 1) * 256 + l * 128 + wt];
    }
    __syncthreads();

    for (int t = 0; t < TPH; t++) {
        // compute tile t (ldmatrix fragment loads)
#pragma unroll
        for (int kc = 0; kc < 2; kc++) {
            const unsigned ko = kc * 32u;     // 8 words = 32 bytes per k8-chunk
            unsigned Ah[2][4], Al[2][4], Bh2[2][4], Bl2[2][4];
#pragma unroll
            for (int mt = 0; mt < 2; mt++) {
                ldsm4(Ah[mt], aAddr[mt] + ko);
                ldsm4(Al[mt], aAddr[mt] + 5120u + ko);
            }
#pragma unroll
            for (int np = 0; np < 2; np++) {
                ldsm4(Bh2[np], bAddr[np] + ko);
                ldsm4(Bl2[np], bAddr[np] + 5120u + ko);
            }
#pragma unroll
            for (int mt = 0; mt < 2; mt++)
#pragma unroll
                for (int nt = 0; nt < 4; nt++) {
                    const int np = nt >> 1, sel = nt & 1;
                    mma16(acc[mt][nt], Ah[mt], Bh2[np][sel], Bh2[np][2 + sel]);
                    mma16(acc[mt][nt], Ah[mt], Bl2[np][sel], Bl2[np][2 + sel]);
                    mma16(acc[mt][nt], Al[mt], Bh2[np][sel], Bh2[np][2 + sel]);
                }
        }
        __syncthreads();

        // stage t+1 from regs; LDG t+2
        if (t + 1 < TPH) {
#pragma unroll
            for (int l = 0; l < 4; l++) {
                int fi = l * 128 + wt;
                int row = fi >> 3, kq = fi & 7;
                unsigned h0, l0, h1, l1;
                split_pack(pa[l].x, pa[l].y, h0, l0);
                split_pack(pa[l].z, pa[l].w, h1, l1);
                *(uint2*)&sAh[row * KPR + 2 * kq] = make_uint2(h0, h1);
                *(uint2*)&sAl[row * KPR + 2 * kq] = make_uint2(l0, l1);
            }
#pragma unroll
            for (int l = 0; l < 2; l++) {
                int u = l * 128 + wt;
                int row = u >> 2, q = u & 3;
                *(uint4*)&sWh[row * KPR + q * 4] = pwh[l];
                *(uint4*)&sWl[row * KPR + q * 4] = pwl[l];
            }
            if (t + 2 < TPH) {
                int k0 = (t + 2) * 8;
#pragma unroll
                for (int l = 0; l < 4; l++) {
                    int fi = l * 128 + wt;
                    int row = fi >> 3, kq = fi & 7;
                    pa[l] = A4[(long)(blk + row) * (DD / 4) + kqb + k0 + kq];
                }
                int w0 = (tb + t + 2) * 256;
#pragma unroll
                for (int l = 0; l < 2; l++) {
                    pwh[l] = gWh4[w0 + l * 128 + wt];
                    pwl[l] = gWl4[w0 + l * 128 + wt];
                }
            }
            __syncthreads();
        }
    }

    // ---- epilogue: half 0 stores partial, half 1 adds ----
    __syncthreads();
    if (h == 0) {
#pragma unroll
        for (int mt = 0; mt < 2; mt++)
#pragma unroll
            for (int nt = 0; nt < 4; nt++) {
                int r  = wm * 32 + mt * 16 + g;
                int cc = wn * 32 + nt * 8 + 2 * c;
                *(float2*)&slog[r * LR + cc]       = make_float2(acc[mt][nt][0], acc[mt][nt][1]);
                *(float2*)&slog[(r + 8) * LR + cc] = make_float2(acc[mt][nt][2], acc[mt][nt][3]);
            }
    }
    __syncthreads();
    if (h == 1) {
#pragma unroll
        for (int mt = 0; mt < 2; mt++)
#pragma unroll
            for (int nt = 0; nt < 4; nt++) {
                int r  = wm * 32 + mt * 16 + g;
                int cc = wn * 32 + nt * 8 + 2 * c;
                float2 v0 = *(float2*)&slog[r * LR + cc];
                float2 v1 = *(float2*)&slog[(r + 8) * LR + cc];
                *(float2*)&slog[r * LR + cc] =
                    make_float2(v0.x + acc[mt][nt][0], v0.y + acc[mt][nt][1]);
                *(float2*)&slog[(r + 8) * LR + cc] =
                    make_float2(v1.x + acc[mt][nt][2], v1.y + acc[mt][nt][3]);
            }
    }
    __syncthreads();

    // zero-fill expert_indices rows for this CTA's 64 tokens (256 threads)
    {
        int tokz = blk + (tid >> 2);
        float4 z = make_float4(0.f, 0.f, 0.f, 0.f);
        float4* zb = (float4*)(out + (long)tokz * EE + (tid & 3) * 16);
#pragma unroll
        for (int q = 0; q < 4; q++) zb[q] = z;
    }

    if (tid < BM) {
        const int tok = blk + tid;
        const float* lr = slog + tid * LR;
        float x[EE];
#pragma unroll
        for (int j = 0; j < 16; j++) {
            float4 v = *(const float4*)(lr + 4 * j);
            float4 b = *(const float4*)(sbias + 4 * j);
            x[4 * j]     = v.x + b.x;
            x[4 * j + 1] = v.y + b.y;
            x[4 * j + 2] = v.z + b.z;
            x[4 * j + 3] = v.w + b.w;
        }
        float mx = -1e30f, mx2 = -1e30f;
        int ag = 0;
#pragma unroll
        for (int j = 0; j < EE; j++) {
            float v = x[j];
            if (v > mx)       { mx2 = mx; mx = v; ag = j; }
            else if (v > mx2) { mx2 = v; }
        }
        float s = 0.0f;
        unsigned long long cmask = 0ull;
        const float thr = mx - TAU_CAND;
#pragma unroll
        for (int j = 0; j < EE; j++) {
            s += __expf(x[j] - mx);
            if (x[j] > thr) cmask |= 1ull << j;
        }
        out[OFF_MAXP + tok] = 1.0f / s;
        g_eidx[tok] = (unsigned char)ag;

        if (mx - mx2 < TAU_FLAG) {
            int p = atomicAdd(&g_cnt, 1);
            if (p < MAXFIX) { g_list[p] = tok; g_mask[p] = cmask; }
        }
    }
}

// One warp per flagged token: exact (fp64) logits for candidate experts only.
__global__ __launch_bounds__(128) void fixup_argmax(
    const float* __restrict__ A, const float* __restrict__ W,
    const float* __restrict__ bias)
{
    int n = g_cnt;
    if (n > MAXFIX) n = MAXFIX;
    const int lane  = threadIdx.x & 31;
    const int warp  = (blockIdx.x * (blockDim.x >> 5)) + (threadIdx.x >> 5);
    const int nwarp = gridDim.x * (blockDim.x >> 5);

    for (int i = warp; i < n; i += nwarp) {
        int tok = g_list[i];
        unsigned long long m = g_mask[i];
        const float* a = A + (long)tok * DD;

        double best = -1e300;
        int bestE = 0;
        while (m) {
            int e = __ffsll((long long)m) - 1;
            m &= m - 1;
            const float* w = W + (long)e * DD;
            double p0 = 0.0, p1 = 0.0, p2 = 0.0, p3 = 0.0;
            for (int k = lane * 4; k < DD; k += 128) {
                float4 av = *(const float4*)(a + k);
                float4 wv = *(const float4*)(w + k);
                p0 = fma((double)av.x, (double)wv.x, p0);
                p1 = fma((double)av.y, (double)wv.y, p1);
                p2 = fma((double)av.z, (double)wv.z, p2);
                p3 = fma((double)av.w, (double)wv.w, p3);
            }
            double ps = (p0 + p1) + (p2 + p3);
#pragma unroll
            for (int d = 16; d > 0; d >>= 1)
                ps += __shfl_xor_sync(0xffffffffu, ps, d);
            ps += (double)bias[e];
            if (ps > best) { best = ps; bestE = e; }
        }
        if (lane == 0) g_eidx[tok] = (unsigned char)bestE;
    }
}

__global__ __launch_bounds__(256) void capacity_scan(float* __restrict__ out)
{
    const int e = blockIdx.x;
    const int b = blockIdx.y;
    const int tid = threadIdx.x;
    const int lane = tid & 31;
    const int wid = tid >> 5;

    const uint4* ids4 = (const uint4*)(g_eidx + b * SS);
    uint4 raw = ids4[tid];
    unsigned char v[16];
    *(uint4*)v = raw;

    int cnum = 0;
#pragma unroll
    for (int j = 0; j < 16; j++) cnum += (v[j] == (unsigned char)e);

    int inc = cnum;
#pragma unroll
    for (int d = 1; d < 32; d <<= 1) {
        int o = __shfl_up_sync(0xffffffffu, inc, d);
        if (lane >= d) inc += o;
    }
    __shared__ int ws[8];
    if (lane == 31) ws[wid] = inc;
    __syncthreads();
    int wpre = 0;
#pragma unroll
    for (int w = 0; w < 8; w++) wpre += (w < wid) ? ws[w] : 0;

    int run = wpre + inc - cnum;
    long tok0 = (long)b * SS + tid * 16;
#pragma unroll
    for (int j = 0; j < 16; j++) {
        if (v[j] == (unsigned char)e) {
            run++;
            if (run <= CAP) out[(tok0 + j) * EE + e] = 1.0f;
        }
    }
    if (e == 0 && b == 0 && tid == 0) g_cnt = 0;
}

extern "C" void kernel_launch(void* const* d_in, const int* in_sizes, int n_in,
                              void* d_out, int out_size)
{
    const float* A    = (const float*)d_in[0];
    const float* W    = (const float*)d_in[1];
    const float* bias = (const float*)d_in[2];
    float* out = (float*)d_out;

    split_w<<<256, 256>>>(W);
    router_mma<<<M_TOT / BM, 256>>>(A, bias, out);
    fixup_argmax<<<148, 128>>>(A, W, bias);
    capacity_scan<<<dim3(EE, BB), 256>>>(out);
}

// round 15
// speedup vs baseline: 1.0538x; 1.0538x over previous
#include <cuda_runtime.h>
#include <cuda_bf16.h>
#include <cstdint>

#define BB 4
#define SS 4096
#define DD 2048
#define EE 64
#define CAP 128
#define M_TOT (BB*SS)          // 16384 tokens
#define OFF_MAXP (M_TOT*EE)

#define BM 64
#define BK 32
#define NTILES (DD/BK)         // 64 total k-tiles
#define TPH 32                 // tiles per k-half (in-CTA split-K=2)
#define KPR 20                 // u32 row stride in smem (conflict-free LDS/LDSM)
#define LR 68                  // slog f32 row stride

#define TAU_FLAG 1e-3f
#define TAU_CAND 2e-3f
#define MAXFIX 8192

// global word permutation: fragment pair (c, c+4) adjacent -> one LDG.64
#define PERM(j) (((j) & 8) | (((j) & 3) << 1) | (((j) >> 2) & 1))

__device__ __align__(16) unsigned char g_eidx[M_TOT];
__device__ int g_cnt = 0;
__device__ int g_list[MAXFIX];
__device__ unsigned long long g_mask[MAXFIX];
// pre-split W, tile-major, PERMUTED: [tile t][row e][16 u32]
__device__ __align__(16) unsigned gWh[NTILES * EE * 16];
__device__ __align__(16) unsigned gWl[NTILES * EE * 16];

// fast split: hi = bf16x2(x,y), lo = bf16x2(residuals); .rn rounding
__device__ __forceinline__ void split_pack(float x, float y, unsigned &hi, unsigned &lo) {
    unsigned H;
    asm("cvt.rn.bf16x2.f32 %0, %1, %2;" : "=r"(H) : "f"(y), "f"(x));
    float xh = __uint_as_float(H << 16);
    float yh = __uint_as_float(H & 0xffff0000u);
    float rx = x - xh, ry = y - yh;
    unsigned L;
    asm("cvt.rn.bf16x2.f32 %0, %1, %2;" : "=r"(L) : "f"(ry), "f"(rx));
    hi = H; lo = L;
}

__device__ __forceinline__ void mma16(float c[4], const unsigned a[4],
                                      unsigned b0, unsigned b1) {
    asm volatile("mma.sync.aligned.m16n8k16.row.col.f32.bf16.bf16.f32 "
                 "{%0,%1,%2,%3}, {%4,%5,%6,%7}, {%8,%9}, {%0,%1,%2,%3};"
                 : "+f"(c[0]), "+f"(c[1]), "+f"(c[2]), "+f"(c[3])
                 : "r"(a[0]), "r"(a[1]), "r"(a[2]), "r"(a[3]), "r"(b0), "r"(b1));
}

__device__ __forceinline__ void ldsm4(unsigned r[4], unsigned addr) {
    asm volatile("ldmatrix.sync.aligned.m8n8.x4.shared.b16 {%0,%1,%2,%3}, [%4];"
                 : "=r"(r[0]), "=r"(r[1]), "=r"(r[2]), "=r"(r[3]) : "r"(addr));
}

__device__ __forceinline__ unsigned smem_u32(const void* p) {
    unsigned a;
    asm("{ .reg .u64 t; cvta.to.shared.u64 t, %1; cvt.u32.u64 %0, t; }" : "=r"(a) : "l"(p));
    return a;
}

__global__ __launch_bounds__(256) void split_w(const float* __restrict__ W)
{
    int e  = blockIdx.x >> 2;
    int jg = (blockIdx.x & 3) * 256 + threadIdx.x;
    int k  = 2 * jg;
    float x = W[e * DD + k], y = W[e * DD + k + 1];
    unsigned h, l;
    split_pack(x, y, h, l);
    int t = jg >> 4, j = jg & 15;
    int jp = PERM(j);
    gWh[(t * EE + e) * 16 + jp] = h;
    gWl[(t * EE + e) * 16 + jp] = l;
}

__global__ __launch_bounds__(256, 2) void router_mma(
    const float* __restrict__ A,     // [M_TOT, DD]
    const float* __restrict__ bias,  // [EE]
    float* __restrict__ out)
{
    __shared__ __align__(16) unsigned smbuf[5120];   // 20 KB: 2 halves x (A h+l)
    __shared__ float sbias[EE];
    float* slog = (float*)smbuf;      // epilogue reuse [64][LR] (4352 words)

    const int tid  = threadIdx.x;
    const int lane = tid & 31;
    const int wid  = tid >> 5;
    const int h    = tid >> 7;        // k-half 0/1
    const int wt   = tid & 127;       // thread within half
    const int w2   = wid & 3;         // warp within half
    const int wm   = w2 >> 1;
    const int wn   = w2 & 1;
    const int g    = lane >> 2;
    const int c    = lane & 3;
    const int blk  = blockIdx.x * BM;

    unsigned* sAh = smbuf + h * 2560;  // [64][KPR]
    unsigned* sAl = sAh + 1280;

    if (tid < EE) sbias[tid] = bias[tid];

    const float4* __restrict__ A4 = (const float4*)A;

    const int kqb = h * (DD / 4 / 2);  // float4 base offset in A row
    const int tb  = h * TPH;           // W tile base for this half

    // per-thread W fragment base (word index into gWh/gWl, excluding tile term)
    const int wfb = (wn * 32 + g) * 16 + 2 * c;

    // ldmatrix lane addresses for A
    const unsigned smb = smem_u32(smbuf);
    const unsigned hb  = smb + h * 10240u;
    const int lrow  = lane & 15;
    const int lhalf = lane >> 4;
    unsigned aAddr[2];
#pragma unroll
    for (int mt = 0; mt < 2; mt++)
        aAddr[mt] = hb + (unsigned)((wm * 32 + mt * 16 + lrow) * 80 + lhalf * 16);

    float acc[2][4][4];
#pragma unroll
    for (int mt = 0; mt < 2; mt++)
#pragma unroll
        for (int nt = 0; nt < 4; nt++)
#pragma unroll
            for (int q = 0; q < 4; q++) acc[mt][nt][q] = 0.0f;

    float4 pa[4];
    uint2  Bh[2][4], Bl[2][4];        // W fragments for current tile (regs)

    // ---- LDG A tile 0 ----
#pragma unroll
    for (int l = 0; l < 4; l++) {
        int fi = l * 128 + wt;
        int row = fi >> 3, kq = fi & 7;
        pa[l] = A4[(long)(blk + row) * (DD / 4) + kqb + kq];
    }
    // ---- stage A tile 0 ----
#pragma unroll
    for (int l = 0; l < 4; l++) {
        int fi = l * 128 + wt;
        int row = fi >> 3, kq = fi & 7;
        unsigned h0, l0, h1, l1;
        split_pack(pa[l].x, pa[l].y, h0, l0);
        split_pack(pa[l].z, pa[l].w, h1, l1);
        *(uint2*)&sAh[row * KPR + 2 * kq] = make_uint2(h0, h1);
        *(uint2*)&sAl[row * KPR + 2 * kq] = make_uint2(l0, l1);
    }
    // ---- LDG A tile 1 ----
#pragma unroll
    for (int l = 0; l < 4; l++) {
        int fi = l * 128 + wt;
        int row = fi >> 3, kq = fi & 7;
        pa[l] = A4[(long)(blk + row) * (DD / 4) + kqb + 8 + kq];
    }
    // ---- W fragments tile 0 (from L2) ----
    {
        int base = tb * (EE * 16) + wfb;
#pragma unroll
        for (int kc = 0; kc < 2; kc++)
#pragma unroll
            for (int nt = 0; nt < 4; nt++) {
                Bh[kc][nt] = *(const uint2*)&gWh[base + nt * 128 + kc * 8];
                Bl[kc][nt] = *(const uint2*)&gWl[base + nt * 128 + kc * 8];
            }
    }
    __syncthreads();

    for (int t = 0; t < TPH; t++) {
        // compute tile t: A via ldmatrix (smem), W from registers
#pragma unroll
        for (int kc = 0; kc < 2; kc++) {
            const unsigned ko = kc * 32u;
            unsigned Ah[2][4], Al[2][4];
#pragma unroll
            for (int mt = 0; mt < 2; mt++) {
                ldsm4(Ah[mt], aAddr[mt] + ko);
                ldsm4(Al[mt], aAddr[mt] + 5120u + ko);
            }
#pragma unroll
            for (int mt = 0; mt < 2; mt++)
#pragma unroll
                for (int nt = 0; nt < 4; nt++) {
                    mma16(acc[mt][nt], Ah[mt], Bh[kc][nt].x, Bh[kc][nt].y);
                    mma16(acc[mt][nt], Ah[mt], Bl[kc][nt].x, Bl[kc][nt].y);
                    mma16(acc[mt][nt], Al[mt], Bh[kc][nt].x, Bh[kc][nt].y);
                }
        }
        // load W fragments for tile t+1 (consume-then-reload, L2-latency slack = 1 tile)
        if (t + 1 < TPH) {
            int base = (tb + t + 1) * (EE * 16) + wfb;
#pragma unroll
            for (int kc = 0; kc < 2; kc++)
#pragma unroll
                for (int nt = 0; nt < 4; nt++) {
                    Bh[kc][nt] = *(const uint2*)&gWh[base + nt * 128 + kc * 8];
                    Bl[kc][nt] = *(const uint2*)&gWl[base + nt * 128 + kc * 8];
                }
        }
        __syncthreads();

        // stage A(t+1) from regs; LDG A(t+2)
        if (t + 1 < TPH) {
#pragma unroll
            for (int l = 0; l < 4; l++) {
                int fi = l * 128 + wt;
                int row = fi >> 3, kq = fi & 7;
                unsigned h0, l0, h1, l1;
                split_pack(pa[l].x, pa[l].y, h0, l0);
                split_pack(pa[l].z, pa[l].w, h1, l1);
                *(uint2*)&sAh[row * KPR + 2 * kq] = make_uint2(h0, h1);
                *(uint2*)&sAl[row * KPR + 2 * kq] = make_uint2(l0, l1);
            }
            if (t + 2 < TPH) {
                int k0 = (t + 2) * 8;
#pragma unroll
                for (int l = 0; l < 4; l++) {
                    int fi = l * 128 + wt;
                    int row = fi >> 3, kq = fi & 7;
                    pa[l] = A4[(long)(blk + row) * (DD / 4) + kqb + k0 + kq];
                }
            }
            __syncthreads();
        }
    }

    // ---- epilogue: half 0 stores partial, half 1 adds ----
    __syncthreads();
    if (h == 0) {
#pragma unroll
        for (int mt = 0; mt < 2; mt++)
#pragma unroll
            for (int nt = 0; nt < 4; nt++) {
                int r  = wm * 32 + mt * 16 + g;
                int cc = wn * 32 + nt * 8 + 2 * c;
                *(float2*)&slog[r * LR + cc]       = make_float2(acc[mt][nt][0], acc[mt][nt][1]);
                *(float2*)&slog[(r + 8) * LR + cc] = make_float2(acc[mt][nt][2], acc[mt][nt][3]);
            }
    }
    __syncthreads();
    if (h == 1) {
#pragma unroll
        for (int mt = 0; mt < 2; mt++)
#pragma unroll
            for (int nt = 0; nt < 4; nt++) {
                int r  = wm * 32 + mt * 16 + g;
                int cc = wn * 32 + nt * 8 + 2 * c;
                float2 v0 = *(float2*)&slog[r * LR + cc];
                float2 v1 = *(float2*)&slog[(r + 8) * LR + cc];
                *(float2*)&slog[r * LR + cc] =
                    make_float2(v0.x + acc[mt][nt][0], v0.y + acc[mt][nt][1]);
                *(float2*)&slog[(r + 8) * LR + cc] =
                    make_float2(v1.x + acc[mt][nt][2], v1.y + acc[mt][nt][3]);
            }
    }
    __syncthreads();

    // zero-fill expert_indices rows for this CTA's 64 tokens (256 threads)
    {
        int tokz = blk + (tid >> 2);
        float4 z = make_float4(0.f, 0.f, 0.f, 0.f);
        float4* zb = (float4*)(out + (long)tokz * EE + (tid & 3) * 16);
#pragma unroll
        for (int q = 0; q < 4; q++) zb[q] = z;
    }

    if (tid < BM) {
        const int tok = blk + tid;
        const float* lr = slog + tid * LR;
        float x[EE];
#pragma unroll
        for (int j = 0; j < 16; j++) {
            float4 v = *(const float4*)(lr + 4 * j);
            float4 b = *(const float4*)(sbias + 4 * j);
            x[4 * j]     = v.x + b.x;
            x[4 * j + 1] = v.y + b.y;
            x[4 * j + 2] = v.z + b.z;
            x[4 * j + 3] = v.w + b.w;
        }
        float mx = -1e30f, mx2 = -1e30f;
        int ag = 0;
#pragma unroll
        for (int j = 0; j < EE; j++) {
            float v = x[j];
            if (v > mx)       { mx2 = mx; mx = v; ag = j; }
            else if (v > mx2) { mx2 = v; }
        }
        float s = 0.0f;
        unsigned long long cmask = 0ull;
        const float thr = mx - TAU_CAND;
#pragma unroll
        for (int j = 0; j < EE; j++) {
            s += __expf(x[j] - mx);
            if (x[j] > thr) cmask |= 1ull << j;
        }
        out[OFF_MAXP + tok] = 1.0f / s;
        g_eidx[tok] = (unsigned char)ag;

        if (mx - mx2 < TAU_FLAG) {
            int p = atomicAdd(&g_cnt, 1);
            if (p < MAXFIX) { g_list[p] = tok; g_mask[p] = cmask; }
        }
    }
}

// One warp per flagged token: exact (fp64) logits for candidate experts only.
__global__ __launch_bounds__(128) void fixup_argmax(
    const float* __restrict__ A, const float* __restrict__ W,
    const float* __restrict__ bias)
{
    int n = g_cnt;
    if (n > MAXFIX) n = MAXFIX;
    const int lane  = threadIdx.x & 31;
    const int warp  = (blockIdx.x * (blockDim.x >> 5)) + (threadIdx.x >> 5);
    const int nwarp = gridDim.x * (blockDim.x >> 5);

    for (int i = warp; i < n; i += nwarp) {
        int tok = g_list[i];
        unsigned long long m = g_mask[i];
        const float* a = A + (long)tok * DD;

        double best = -1e300;
        int bestE = 0;
        while (m) {
            int e = __ffsll((long long)m) - 1;
            m &= m - 1;
            const float* w = W + (long)e * DD;
            double p0 = 0.0, p1 = 0.0, p2 = 0.0, p3 = 0.0;
            for (int k = lane * 4; k < DD; k += 128) {
                float4 av = *(const float4*)(a + k);
                float4 wv = *(const float4*)(w + k);
                p0 = fma((double)av.x, (double)wv.x, p0);
                p1 = fma((double)av.y, (double)wv.y, p1);
                p2 = fma((double)av.z, (double)wv.z, p2);
                p3 = fma((double)av.w, (double)wv.w, p3);
            }
            double ps = (p0 + p1) + (p2 + p3);
#pragma unroll
            for (int d = 16; d > 0; d >>= 1)
                ps += __shfl_xor_sync(0xffffffffu, ps, d);
            ps += (double)bias[e];
            if (ps > best) { best = ps; bestE = e; }
        }
        if (lane == 0) g_eidx[tok] = (unsigned char)bestE;
    }
}

__global__ __launch_bounds__(256) void capacity_scan(float* __restrict__ out)
{
    const int e = blockIdx.x;
    const int b = blockIdx.y;
    const int tid = threadIdx.x;
    const int lane = tid & 31;
    const int wid = tid >> 5;

    const uint4* ids4 = (const uint4*)(g_eidx + b * SS);
    uint4 raw = ids4[tid];
    unsigned char v[16];
    *(uint4*)v = raw;

    int cnum = 0;
#pragma unroll
    for (int j = 0; j < 16; j++) cnum += (v[j] == (unsigned char)e);

    int inc = cnum;
#pragma unroll
    for (int d = 1; d < 32; d <<= 1) {
        int o = __shfl_up_sync(0xffffffffu, inc, d);
        if (lane >= d) inc += o;
    }
    __shared__ int ws[8];
    if (lane == 31) ws[wid] = inc;
    __syncthreads();
    int wpre = 0;
#pragma unroll
    for (int w = 0; w < 8; w++) wpre += (w < wid) ? ws[w] : 0;

    int run = wpre + inc - cnum;
    long tok0 = (long)b * SS + tid * 16;
#pragma unroll
    for (int j = 0; j < 16; j++) {
        if (v[j] == (unsigned char)e) {
            run++;
            if (run <= CAP) out[(tok0 + j) * EE + e] = 1.0f;
        }
    }
    if (e == 0 && b == 0 && tid == 0) g_cnt = 0;
}

extern "C" void kernel_launch(void* const* d_in, const int* in_sizes, int n_in,
                              void* d_out, int out_size)
{
    const float* A    = (const float*)d_in[0];
    const float* W    = (const float*)d_in[1];
    const float* bias = (const float*)d_in[2];
    float* out = (float*)d_out;

    split_w<<<256, 256>>>(W);
    router_mma<<<M_TOT / BM, 256>>>(A, bias, out);
    fixup_argmax<<<148, 128>>>(A, W, bias);
    capacity_scan<<<dim3(EE, BB), 256>>>(out);
}

// round 16
// speedup vs baseline: 1.0722x; 1.0175x over previous
#include <cuda_runtime.h>
#include <cuda_bf16.h>
#include <cstdint>

#define BB 4
#define SS 4096
#define DD 2048
#define EE 64
#define CAP 128
#define M_TOT (BB*SS)          // 16384 tokens
#define OFF_MAXP (M_TOT*EE)

#define BM 64
#define BK 32
#define NTILES (DD/BK)         // 64 total k-tiles
#define TPH 32                 // tiles per k-half (in-CTA split-K=2)
#define KPR 20                 // u32 row stride in smem (conflict-free LDS/LDSM)
#define LR 68                  // slog f32 row stride

#define TAU_FLAG 1e-3f
#define TAU_CAND 2e-3f
#define MAXFIX 8192

// global word permutation: fragment pair (c, c+4) adjacent -> one LDG.64
#define PERM(j) (((j) & 8) | (((j) & 3) << 1) | (((j) >> 2) & 1))

__device__ __align__(16) unsigned char g_eidx[M_TOT];
__device__ int g_cnt = 0;
__device__ int g_list[MAXFIX];
__device__ unsigned long long g_mask[MAXFIX];
// pre-split W, tile-major, PERMUTED: [tile t][row e][16 u32]
__device__ __align__(16) unsigned gWh[NTILES * EE * 16];
__device__ __align__(16) unsigned gWl[NTILES * EE * 16];

// fast split: hi = bf16x2(x,y), lo = bf16x2(residuals); .rn rounding
__device__ __forceinline__ void split_pack(float x, float y, unsigned &hi, unsigned &lo) {
    unsigned H;
    asm("cvt.rn.bf16x2.f32 %0, %1, %2;" : "=r"(H) : "f"(y), "f"(x));
    float xh = __uint_as_float(H << 16);
    float yh = __uint_as_float(H & 0xffff0000u);
    float rx = x - xh, ry = y - yh;
    unsigned L;
    asm("cvt.rn.bf16x2.f32 %0, %1, %2;" : "=r"(L) : "f"(ry), "f"(rx));
    hi = H; lo = L;
}

__device__ __forceinline__ void mma16(float c[4], const unsigned a[4],
                                      unsigned b0, unsigned b1) {
    asm volatile("mma.sync.aligned.m16n8k16.row.col.f32.bf16.bf16.f32 "
                 "{%0,%1,%2,%3}, {%4,%5,%6,%7}, {%8,%9}, {%0,%1,%2,%3};"
                 : "+f"(c[0]), "+f"(c[1]), "+f"(c[2]), "+f"(c[3])
                 : "r"(a[0]), "r"(a[1]), "r"(a[2]), "r"(a[3]), "r"(b0), "r"(b1));
}

__device__ __forceinline__ void ldsm4(unsigned r[4], unsigned addr) {
    asm volatile("ldmatrix.sync.aligned.m8n8.x4.shared.b16 {%0,%1,%2,%3}, [%4];"
                 : "=r"(r[0]), "=r"(r[1]), "=r"(r[2]), "=r"(r[3]) : "r"(addr));
}

__device__ __forceinline__ unsigned smem_u32(const void* p) {
    unsigned a;
    asm("{ .reg .u64 t; cvta.to.shared.u64 t, %1; cvt.u32.u64 %0, t; }" : "=r"(a) : "l"(p));
    return a;
}

__global__ __launch_bounds__(256) void split_w(const float* __restrict__ W)
{
    int e  = blockIdx.x >> 2;
    int jg = (blockIdx.x & 3) * 256 + threadIdx.x;
    int k  = 2 * jg;
    float x = W[e * DD + k], y = W[e * DD + k + 1];
    unsigned h, l;
    split_pack(x, y, h, l);
    int t = jg >> 4, j = jg & 15;
    int jp = PERM(j);
    gWh[(t * EE + e) * 16 + jp] = h;
    gWl[(t * EE + e) * 16 + jp] = l;
}

__global__ __launch_bounds__(256, 2) void router_mma(
    const float* __restrict__ A,     // [M_TOT, DD]
    const float* __restrict__ bias,  // [EE]
    float* __restrict__ out)
{
    // 40 KB: half h at word h*5120; buf b at +b*2560; sAh[1280] then sAl[1280]
    __shared__ __align__(16) unsigned smbuf[10240];
    __shared__ float sbias[EE];
    float* slog = (float*)smbuf;      // epilogue reuse [64][LR] (4352 words)

    const int tid  = threadIdx.x;
    const int lane = tid & 31;
    const int wid  = tid >> 5;
    const int h    = tid >> 7;        // k-half 0/1
    const int wt   = tid & 127;       // thread within half
    const int w2   = wid & 3;         // warp within half
    const int wm   = w2 >> 1;
    const int wn   = w2 & 1;
    const int g    = lane >> 2;
    const int c    = lane & 3;
    const int blk  = blockIdx.x * BM;

    if (tid < EE) sbias[tid] = bias[tid];

    const float4* __restrict__ A4 = (const float4*)A;

    const int kqb = h * (DD / 4 / 2);  // float4 base offset in A row
    const int tb  = h * TPH;           // W tile base for this half

    // per-thread W fragment base (word index into gWh/gWl, excluding tile term)
    const int wfb = (wn * 32 + g) * 16 + 2 * c;

    // ldmatrix lane base addresses for A (add buf*10240 bytes at use)
    const unsigned smb = smem_u32(smbuf);
    const unsigned hb  = smb + h * 20480u;
    const int lrow  = lane & 15;
    const int lhalf = lane >> 4;
    unsigned aAddr[2];
#pragma unroll
    for (int mt = 0; mt < 2; mt++)
        aAddr[mt] = hb + (unsigned)((wm * 32 + mt * 16 + lrow) * 80 + lhalf * 16);

    // staging smem word bases (add buf*2560 at use)
    unsigned* sAh0 = smbuf + h * 5120;
    unsigned* sAl0 = sAh0 + 1280;

    float acc[2][4][4];
#pragma unroll
    for (int mt = 0; mt < 2; mt++)
#pragma unroll
        for (int nt = 0; nt < 4; nt++)
#pragma unroll
            for (int q = 0; q < 4; q++) acc[mt][nt][q] = 0.0f;

    float4 pa[4];
    uint2  Bh[2][4], Bl[2][4];        // W fragments for current tile (regs)

    const int arow = wt >> 3, akq = wt & 7;   // staging indices (row, kq) per l

    // ---- LDG A tile 0; stage into buf0 ----
#pragma unroll
    for (int l = 0; l < 4; l++) {
        int fi = l * 128 + wt;
        int row = fi >> 3, kq = fi & 7;
        pa[l] = A4[(long)(blk + row) * (DD / 4) + kqb + kq];
    }
#pragma unroll
    for (int l = 0; l < 4; l++) {
        int fi = l * 128 + wt;
        int row = fi >> 3, kq = fi & 7;
        unsigned h0, l0, h1, l1;
        split_pack(pa[l].x, pa[l].y, h0, l0);
        split_pack(pa[l].z, pa[l].w, h1, l1);
        *(uint2*)&sAh0[row * KPR + 2 * kq] = make_uint2(h0, h1);
        *(uint2*)&sAl0[row * KPR + 2 * kq] = make_uint2(l0, l1);
    }
    // ---- LDG A tile 1 ----
#pragma unroll
    for (int l = 0; l < 4; l++) {
        int fi = l * 128 + wt;
        int row = fi >> 3, kq = fi & 7;
        pa[l] = A4[(long)(blk + row) * (DD / 4) + kqb + 8 + kq];
    }
    // ---- W fragments tile 0 (from L2) ----
    {
        int base = tb * (EE * 16) + wfb;
#pragma unroll
        for (int kc = 0; kc < 2; kc++)
#pragma unroll
            for (int nt = 0; nt < 4; nt++) {
                Bh[kc][nt] = *(const uint2*)&gWh[base + nt * 128 + kc * 8];
                Bl[kc][nt] = *(const uint2*)&gWl[base + nt * 128 + kc * 8];
            }
    }
    __syncthreads();

    for (int t = 0; t < TPH; t++) {
        const int buf = t & 1;
        const unsigned bOff = (unsigned)(buf ^ 1) * 2560u;

        // stage A(t+1) into other buffer (pa holds tile t+1)
        if (t + 1 < TPH) {
            unsigned* dAh = sAh0 + bOff;
            unsigned* dAl = sAl0 + bOff;
#pragma unroll
            for (int l = 0; l < 4; l++) {
                int fi = l * 128 + wt;
                int row = fi >> 3, kq = fi & 7;
                unsigned h0, l0, h1, l1;
                split_pack(pa[l].x, pa[l].y, h0, l0);
                split_pack(pa[l].z, pa[l].w, h1, l1);
                *(uint2*)&dAh[row * KPR + 2 * kq] = make_uint2(h0, h1);
                *(uint2*)&dAl[row * KPR + 2 * kq] = make_uint2(l0, l1);
            }
            // LDG A(t+2)
            if (t + 2 < TPH) {
                int k0 = (t + 2) * 8;
#pragma unroll
                for (int l = 0; l < 4; l++) {
                    int fi = l * 128 + wt;
                    int row = fi >> 3, kq = fi & 7;
                    pa[l] = A4[(long)(blk + row) * (DD / 4) + kqb + k0 + kq];
                }
            }
        }

        // compute tile t from current buffer; W from registers
        const unsigned cOff = (unsigned)buf * 10240u;
#pragma unroll
        for (int kc = 0; kc < 2; kc++) {
            const unsigned ko = kc * 32u + cOff;
            unsigned Ah[2][4], Al[2][4];
#pragma unroll
            for (int mt = 0; mt < 2; mt++) {
                ldsm4(Ah[mt], aAddr[mt] + ko);
                ldsm4(Al[mt], aAddr[mt] + 5120u + ko);
            }
#pragma unroll
            for (int mt = 0; mt < 2; mt++)
#pragma unroll
                for (int nt = 0; nt < 4; nt++) {
                    mma16(acc[mt][nt], Ah[mt], Bh[kc][nt].x, Bh[kc][nt].y);
                    mma16(acc[mt][nt], Ah[mt], Bl[kc][nt].x, Bl[kc][nt].y);
                    mma16(acc[mt][nt], Al[mt], Bh[kc][nt].x, Bh[kc][nt].y);
                }
        }

        // load W fragments for tile t+1 (consume-then-reload)
        if (t + 1 < TPH) {
            int base = (tb + t + 1) * (EE * 16) + wfb;
#pragma unroll
            for (int kc = 0; kc < 2; kc++)
#pragma unroll
                for (int nt = 0; nt < 4; nt++) {
                    Bh[kc][nt] = *(const uint2*)&gWh[base + nt * 128 + kc * 8];
                    Bl[kc][nt] = *(const uint2*)&gWl[base + nt * 128 + kc * 8];
                }
        }
        __syncthreads();
    }

    // ---- epilogue: half 0 stores partial, half 1 adds ----
    if (h == 0) {
#pragma unroll
        for (int mt = 0; mt < 2; mt++)
#pragma unroll
            for (int nt = 0; nt < 4; nt++) {
                int r  = wm * 32 + mt * 16 + g;
                int cc = wn * 32 + nt * 8 + 2 * c;
                *(float2*)&slog[r * LR + cc]       = make_float2(acc[mt][nt][0], acc[mt][nt][1]);
                *(float2*)&slog[(r + 8) * LR + cc] = make_float2(acc[mt][nt][2], acc[mt][nt][3]);
            }
    }
    __syncthreads();
    if (h == 1) {
#pragma unroll
        for (int mt = 0; mt < 2; mt++)
#pragma unroll
            for (int nt = 0; nt < 4; nt++) {
                int r  = wm * 32 + mt * 16 + g;
                int cc = wn * 32 + nt * 8 + 2 * c;
                float2 v0 = *(float2*)&slog[r * LR + cc];
                float2 v1 = *(float2*)&slog[(r + 8) * LR + cc];
                *(float2*)&slog[r * LR + cc] =
                    make_float2(v0.x + acc[mt][nt][0], v0.y + acc[mt][nt][1]);
                *(float2*)&slog[(r + 8) * LR + cc] =
                    make_float2(v1.x + acc[mt][nt][2], v1.y + acc[mt][nt][3]);
            }
    }
    __syncthreads();

    // zero-fill expert_indices rows for this CTA's 64 tokens (256 threads)
    {
        int tokz = blk + (tid >> 2);
        float4 z = make_float4(0.f, 0.f, 0.f, 0.f);
        float4* zb = (float4*)(out + (long)tokz * EE + (tid & 3) * 16);
#pragma unroll
        for (int q = 0; q < 4; q++) zb[q] = z;
    }

    if (tid < BM) {
        const int tok = blk + tid;
        const float* lr = slog + tid * LR;
        float x[EE];
#pragma unroll
        for (int j = 0; j < 16; j++) {
            float4 v = *(const float4*)(lr + 4 * j);
            float4 b = *(const float4*)(sbias + 4 * j);
            x[4 * j]     = v.x + b.x;
            x[4 * j + 1] = v.y + b.y;
            x[4 * j + 2] = v.z + b.z;
            x[4 * j + 3] = v.w + b.w;
        }
        float mx = -1e30f, mx2 = -1e30f;
        int ag = 0;
#pragma unroll
        for (int j = 0; j < EE; j++) {
            float v = x[j];
            if (v > mx)       { mx2 = mx; mx = v; ag = j; }
            else if (v > mx2) { mx2 = v; }
        }
        float s = 0.0f;
        unsigned long long cmask = 0ull;
        const float thr = mx - TAU_CAND;
#pragma unroll
        for (int j = 0; j < EE; j++) {
            s += __expf(x[j] - mx);
            if (x[j] > thr) cmask |= 1ull << j;
        }
        out[OFF_MAXP + tok] = 1.0f / s;
        g_eidx[tok] = (unsigned char)ag;

        if (mx - mx2 < TAU_FLAG) {
            int p = atomicAdd(&g_cnt, 1);
            if (p < MAXFIX) { g_list[p] = tok; g_mask[p] = cmask; }
        }
    }
}

// One warp per flagged token: exact (fp64) logits for candidate experts only.
__global__ __launch_bounds__(128) void fixup_argmax(
    const float* __restrict__ A, const float* __restrict__ W,
    const float* __restrict__ bias)
{
    int n = g_cnt;
    if (n > MAXFIX) n = MAXFIX;
    const int lane  = threadIdx.x & 31;
    const int warp  = (blockIdx.x * (blockDim.x >> 5)) + (threadIdx.x >> 5);
    const int nwarp = gridDim.x * (blockDim.x >> 5);

    for (int i = warp; i < n; i += nwarp) {
        int tok = g_list[i];
        unsigned long long m = g_mask[i];
        const float* a = A + (long)tok * DD;

        double best = -1e300;
        int bestE = 0;
        while (m) {
            int e = __ffsll((long long)m) - 1;
            m &= m - 1;
            const float* w = W + (long)e * DD;
            double p0 = 0.0, p1 = 0.0, p2 = 0.0, p3 = 0.0;
            for (int k = lane * 4; k < DD; k += 128) {
                float4 av = *(const float4*)(a + k);
                float4 wv = *(const float4*)(w + k);
                p0 = fma((double)av.x, (double)wv.x, p0);
                p1 = fma((double)av.y, (double)wv.y, p1);
                p2 = fma((double)av.z, (double)wv.z, p2);
                p3 = fma((double)av.w, (double)wv.w, p3);
            }
            double ps = (p0 + p1) + (p2 + p3);
#pragma unroll
            for (int d = 16; d > 0; d >>= 1)
                ps += __shfl_xor_sync(0xffffffffu, ps, d);
            ps += (double)bias[e];
            if (ps > best) { best = ps; bestE = e; }
        }
        if (lane == 0) g_eidx[tok] = (unsigned char)bestE;
    }
}

__global__ __launch_bounds__(256) void capacity_scan(float* __restrict__ out)
{
    const int e = blockIdx.x;
    const int b = blockIdx.y;
    const int tid = threadIdx.x;
    const int lane = tid & 31;
    const int wid = tid >> 5;

    const uint4* ids4 = (const uint4*)(g_eidx + b * SS);
    uint4 raw = ids4[tid];
    unsigned char v[16];
    *(uint4*)v = raw;

    int cnum = 0;
#pragma unroll
    for (int j = 0; j < 16; j++) cnum += (v[j] == (unsigned char)e);

    int inc = cnum;
#pragma unroll
    for (int d = 1; d < 32; d <<= 1) {
        int o = __shfl_up_sync(0xffffffffu, inc, d);
        if (lane >= d) inc += o;
    }
    __shared__ int ws[8];
    if (lane == 31) ws[wid] = inc;
    __syncthreads();
    int wpre = 0;
#pragma unroll
    for (int w = 0; w < 8; w++) wpre += (w < wid) ? ws[w] : 0;

    int run = wpre + inc - cnum;
    long tok0 = (long)b * SS + tid * 16;
#pragma unroll
    for (int j = 0; j < 16; j++) {
        if (v[j] == (unsigned char)e) {
            run++;
            if (run <= CAP) out[(tok0 + j) * EE + e] = 1.0f;
        }
    }
    if (e == 0 && b == 0 && tid == 0) g_cnt = 0;
}

extern "C" void kernel_launch(void* const* d_in, const int* in_sizes, int n_in,
                              void* d_out, int out_size)
{
    const float* A    = (const float*)d_in[0];
    const float* W    = (const float*)d_in[1];
    const float* bias = (const float*)d_in[2];
    float* out = (float*)d_out;

    split_w<<<256, 256>>>(W);
    router_mma<<<M_TOT / BM, 256>>>(A, bias, out);
    fixup_argmax<<<148, 128>>>(A, W, bias);
    capacity_scan<<<dim3(EE, BB), 256>>>(out);
}